// round 9
// baseline (speedup 1.0000x reference)
#include <cuda_runtime.h>
#include <cstdint>
#include <cstddef>

typedef unsigned long long ull;

#define Tlen   512
#define NB     4096
#define NTHR   512          // 16 warps: 4 per layer
#define NTICKS (Tlen + 4)   // layer l does t=T-l; fc does t=T-4
#define CLU    2            // cluster size; each cluster handles 64 batches

// ---- shared memory layout (float offsets), all 16B-aligned ----
#define W0_OFF    0                    // 100 rows x 28  = 2800  : L1 fused [Wih1|Whh1|pad2]
#define W123_OFF  2800                 // 3 x 100 x 52   = 15600 : L2-4 fused [Wih|0|Whh|0]
#define BIAS_OFF  (W123_OFF + 15600)   // 18400 : [4 layer][25 unit][4 gate] fused bih+bhh
#define WFC_OFF   (BIAS_OFF + 400)     // 18800 : 52-float fc row (W_fc at [26..50])
#define V0_OFF    (WFC_OFF + 52)       // 18852 : [2 set][2 buf][32 lane][28]
#define V0_SET    1792
#define V123_OFF  (V0_OFF + 2 * V0_SET)   // 22436 : [2 set][3 layer][2 buf][32][52]
#define V123_SET  9984
#define SMEM_FLOATS (V123_OFF + 2 * V123_SET)  // 42404 floats = 169616 bytes

__device__ __forceinline__ ull pack2(float lo, float hi) {
    return (ull)__float_as_uint(lo) | ((ull)__float_as_uint(hi) << 32);
}
__device__ __forceinline__ float hsum2(ull v) {
    float lo = __uint_as_float((unsigned)v);
    float hi = __uint_as_float((unsigned)(v >> 32));
    return lo + hi;
}
__device__ __forceinline__ void fma2(ull& acc, ull a, ull b) {
    asm("fma.rn.f32x2 %0, %1, %2, %0;" : "+l"(acc) : "l"(a), "l"(b));
}
__device__ __forceinline__ float fast_sig(float x) {
    float e, r;
    asm("ex2.approx.ftz.f32 %0, %1;" : "=f"(e) : "f"(x * -1.4426950408889634f));
    asm("rcp.approx.ftz.f32 %0, %1;" : "=f"(r) : "f"(e + 1.0f));
    return r;
}
__device__ __forceinline__ float fast_tanh(float x) {
    return fmaf(2.0f, fast_sig(2.0f * x), -1.0f);
}
__device__ __forceinline__ uint32_t smem_u32(const void* p) {
    uint32_t a;
    asm("{ .reg .u64 t; cvta.to.shared.u64 t, %1; cvt.u32.u64 %0, t; }" : "=r"(a) : "l"(p));
    return a;
}
__device__ __forceinline__ uint32_t my_ctarank() {
    uint32_t r; asm("mov.u32 %0, %%cluster_ctarank;" : "=r"(r)); return r;
}
__device__ __forceinline__ uint32_t mapa_u32(uint32_t addr, uint32_t rank) {
    uint32_t r;
    asm("mapa.shared::cluster.u32 %0, %1, %2;" : "=r"(r) : "r"(addr), "r"(rank));
    return r;
}
__device__ __forceinline__ void st_cluster_f32(uint32_t addr, float v) {
    asm volatile("st.shared::cluster.f32 [%0], %1;" :: "r"(addr), "f"(v) : "memory");
}
__device__ __forceinline__ void cluster_arrive() {
    asm volatile("barrier.cluster.arrive.aligned;" ::: "memory");
}
__device__ __forceinline__ void cluster_wait() {
    asm volatile("barrier.cluster.wait.aligned;" ::: "memory");
}

// 4-gate dot products for one unit, v-row already in registers.
template<int NCH>
__device__ __forceinline__ void gates4reg(const ulonglong2* __restrict__ V,
    const float* __restrict__ w0, const float* __restrict__ w1,
    const float* __restrict__ w2, const float* __restrict__ w3,
    float b0, float b1, float b2, float b3,
    float& s0, float& s1, float& s2, float& s3)
{
    ull A0 = pack2(b0, 0.f), B0 = 0ull;
    ull A1 = pack2(b1, 0.f), B1 = 0ull;
    ull A2 = pack2(b2, 0.f), B2 = 0ull;
    ull A3 = pack2(b3, 0.f), B3 = 0ull;
    const ulonglong2* W0 = (const ulonglong2*)w0;
    const ulonglong2* W1 = (const ulonglong2*)w1;
    const ulonglong2* W2 = (const ulonglong2*)w2;
    const ulonglong2* W3 = (const ulonglong2*)w3;
#pragma unroll
    for (int ch = 0; ch < NCH; ++ch) {
        ulonglong2 w;
        w = W0[ch]; fma2(A0, w.x, V[ch].x); fma2(B0, w.y, V[ch].y);
        w = W1[ch]; fma2(A1, w.x, V[ch].x); fma2(B1, w.y, V[ch].y);
        w = W2[ch]; fma2(A2, w.x, V[ch].x); fma2(B2, w.y, V[ch].y);
        w = W3[ch]; fma2(A3, w.x, V[ch].x); fma2(B3, w.y, V[ch].y);
    }
    s0 = hsum2(A0) + hsum2(B0);
    s1 = hsum2(A1) + hsum2(B1);
    s2 = hsum2(A2) + hsum2(B2);
    s3 = hsum2(A3) + hsum2(B3);
}

__global__ void __launch_bounds__(NTHR) __cluster_dims__(CLU, 1, 1) lstm_kernel(
    const float* __restrict__ x,
    const float* __restrict__ Wih1, const float* __restrict__ Whh1,
    const float* __restrict__ bih1, const float* __restrict__ bhh1,
    const float* __restrict__ Wih2, const float* __restrict__ Whh2,
    const float* __restrict__ bih2, const float* __restrict__ bhh2,
    const float* __restrict__ Wih3, const float* __restrict__ Whh3,
    const float* __restrict__ bih3, const float* __restrict__ bhh3,
    const float* __restrict__ Wih4, const float* __restrict__ Whh4,
    const float* __restrict__ bih4, const float* __restrict__ bhh4,
    const float* __restrict__ Wfc, const float* __restrict__ bfc,
    float* __restrict__ out, int write_states)
{
    extern __shared__ float smem[];
    const int tid = threadIdx.x;

    // ---- stage fused weights (full copy in each block; reads filtered by ownership) ----
    for (int i = tid; i < 2800; i += NTHR) {
        int g = i / 28, p = i - g * 28;
        float v = 0.f;
        if (p == 0)      v = Wih1[g];
        else if (p < 26) v = Whh1[g * 25 + p - 1];
        smem[W0_OFF + i] = v;
    }
    {
        const float* WihL[3] = {Wih2, Wih3, Wih4};
        const float* WhhL[3] = {Whh2, Whh3, Whh4};
        for (int i = tid; i < 15600; i += NTHR) {
            int l = i / 5200; int r = i - l * 5200;
            int g = r / 52,   p = r - g * 52;
            float v = 0.f;
            if (p < 25)                 v = WihL[l][g * 25 + p];
            else if (p >= 26 && p < 51) v = WhhL[l][g * 25 + p - 26];
            smem[W123_OFF + i] = v;
        }
        const float* bi[4] = {bih1, bih2, bih3, bih4};
        const float* bh[4] = {bhh1, bhh2, bhh3, bhh4};
        for (int i = tid; i < 400; i += NTHR) {
            int l = i / 100, r = i - l * 100, u = r >> 2, j = r & 3;
            smem[BIAS_OFF + i] = bi[l][j * 25 + u] + bh[l][j * 25 + u];
        }
    }
    for (int i = tid; i < 52; i += NTHR)
        smem[WFC_OFF + i] = (i >= 26 && i < 51) ? Wfc[i - 26] : 0.f;
    for (int i = tid; i < 2 * V0_SET + 2 * V123_SET; i += NTHR) smem[V0_OFF + i] = 0.f;

    const int lane  = tid & 31;
    const int wid   = tid >> 5;
    const int layer = wid >> 2;                       // 0..3
    const int wl    = wid & 3;                        // warp-in-layer
    const uint32_t rank = my_ctarank();               // 0 or 1
    // unit ownership: rank0 -> 0..12 (13 units, split 3,3,3,4); rank1 -> 13..24 (3,3,3,3)
    const int ubase = rank ? 13 : 0;
    const int uown  = rank ? 12 : 13;
    const int first = ubase + (wl * uown) / 4;
    const int nu    = ubase + ((wl + 1) * uown) / 4 - first;

    const int cb   = (blockIdx.x >> 1) * 64;          // cluster batch base
    const int gbS[2] = { cb + lane, cb + 32 + lane }; // global batch per set

    const uint32_t base_u32 = smem_u32(smem);
    const uint32_t peer_u32 = mapa_u32(base_u32, rank ^ 1);

    float xreg[2] = {0.f, 0.f};
    float bfc_reg = 0.f;
    if (wid == 0) {
        smem[V0_OFF + 0 * V0_SET + lane * 28 + 0] = x[gbS[0]];     // x(0)
        smem[V0_OFF + 1 * V0_SET + lane * 28 + 0] = x[gbS[1]];
        xreg[0] = x[(size_t)NB + gbS[0]];                          // prefetch x(1)
        xreg[1] = x[(size_t)NB + gbS[1]];
    }
    if (rank == 0 && wid == 1) bfc_reg = bfc[0];
    __syncthreads();
    cluster_arrive(); cluster_wait();    // both blocks init'd before any remote write

    float c[8];                           // c[set*4 + k]
#pragma unroll
    for (int i = 0; i < 8; ++i) c[i] = 0.f;

    // per-set row bases (float index into smem), this lane's row
    int rowIdx[2];                        // v-row base for this warp's layer
    int childIdx[2];                      // next layer's row base (input slots)
#pragma unroll
    for (int s = 0; s < 2; ++s) {
        rowIdx[s] = (layer == 0)
            ? V0_OFF + s * V0_SET + lane * 28
            : V123_OFF + s * V123_SET + (layer - 1) * 3328 + lane * 52;
        childIdx[s] = (layer < 3)
            ? V123_OFF + s * V123_SET + layer * 3328 + lane * 52
            : 0;
    }
    const float* biasS = smem + BIAS_OFF + layer * 100;
    const float* wfc   = smem + WFC_OFF;

    for (int T = 0; T < NTICKS; ++T) {
        const int par = (T + layer) & 1;

        // ---- x stager (warp 0 of each block): stage x(T+1), prefetch x(T+2) ----
        if (wid == 0) {
            int nb = (T + 1) & 1;
            smem[V0_OFF + 0 * V0_SET + nb * 896 + lane * 28] = xreg[0];
            smem[V0_OFF + 1 * V0_SET + nb * 896 + lane * 28] = xreg[1];
            int t2 = (T + 2 < Tlen) ? T + 2 : Tlen - 1;
            xreg[0] = x[(size_t)t2 * NB + gbS[0]];
            xreg[1] = x[(size_t)t2 * NB + gbS[1]];
        }
        // ---- fc (rank 0, warp 1): y(T-4) from h4(T-4) in v3 buffer (T+1)&1 ----
        if (rank == 0 && wid == 1 && T >= 4) {
#pragma unroll
            for (int s = 0; s < 2; ++s) {
                const float* v3 = smem + V123_OFF + s * V123_SET + 2 * 3328
                                + lane * 52 + ((T + 1) & 1) * 1664;
                const ulonglong2* V3 = (const ulonglong2*)v3;
                const ulonglong2* WF = (const ulonglong2*)wfc;
                ull A = pack2(bfc_reg, 0.f), B = 0ull;
#pragma unroll
                for (int ch = 6; ch < 13; ++ch) {
                    ulonglong2 hv = V3[ch]; ulonglong2 w = WF[ch];
                    fma2(A, w.x, hv.x); fma2(B, w.y, hv.y);
                }
                out[(size_t)(T - 4) * NB + gbS[s]] = hsum2(A) + hsum2(B);
            }
        }

        const bool act = (T >= layer) && (T - layer < Tlen);
        if (act) {
#pragma unroll
            for (int s = 0; s < 2; ++s) {
                if (layer == 0) {
                    ulonglong2 V[7];
                    const ulonglong2* src = (const ulonglong2*)(smem + rowIdx[s] + par * 896);
#pragma unroll
                    for (int ch = 0; ch < 7; ++ch) V[ch] = src[ch];
#pragma unroll
                    for (int k = 0; k < 4; ++k) if (k < nu) {
                        const int u = first + k;
                        const float* wr = smem + W0_OFF + u * 28;
                        float4 bb = *(const float4*)(biasS + u * 4);
                        float s0, s1, s2, s3;
                        gates4reg<7>(V, wr, wr + 700, wr + 1400, wr + 2100,
                                     bb.x, bb.y, bb.z, bb.w, s0, s1, s2, s3);
                        float fi = fast_sig(s0), ff = fast_sig(s1);
                        float fg = fast_tanh(s2), fo = fast_sig(s3);
                        c[s * 4 + k] = fmaf(ff, c[s * 4 + k], fi * fg);
                        float h = fo * fast_tanh(c[s * 4 + k]);
                        int iSelf  = rowIdx[s] + (par ^ 1) * 896 + 1 + u;
                        int iChild = childIdx[s] + par * 1664 + u;
                        smem[iSelf]  = h; st_cluster_f32(peer_u32 + iSelf * 4, h);
                        smem[iChild] = h; st_cluster_f32(peer_u32 + iChild * 4, h);
                    }
                } else {
                    ulonglong2 V[13];
                    const ulonglong2* src = (const ulonglong2*)(smem + rowIdx[s] + par * 1664);
#pragma unroll
                    for (int ch = 0; ch < 13; ++ch) V[ch] = src[ch];
#pragma unroll
                    for (int k = 0; k < 4; ++k) if (k < nu) {
                        const int u = first + k;
                        const float* wr = smem + W123_OFF + (layer - 1) * 5200 + u * 52;
                        float4 bb = *(const float4*)(biasS + u * 4);
                        float s0, s1, s2, s3;
                        gates4reg<13>(V, wr, wr + 1300, wr + 2600, wr + 3900,
                                      bb.x, bb.y, bb.z, bb.w, s0, s1, s2, s3);
                        float fi = fast_sig(s0), ff = fast_sig(s1);
                        float fg = fast_tanh(s2), fo = fast_sig(s3);
                        c[s * 4 + k] = fmaf(ff, c[s * 4 + k], fi * fg);
                        float h = fo * fast_tanh(c[s * 4 + k]);
                        int iSelf = rowIdx[s] + (par ^ 1) * 1664 + 26 + u;
                        smem[iSelf] = h; st_cluster_f32(peer_u32 + iSelf * 4, h);
                        if (layer < 3) {
                            int iChild = childIdx[s] + par * 1664 + u;
                            smem[iChild] = h; st_cluster_f32(peer_u32 + iChild * 4, h);
                        }
                    }
                }
            }
        }
        cluster_arrive();   // release: local + remote SMEM writes visible after wait
        cluster_wait();
    }

    // ---- final states (h1,c1,h2,c2,h3,c3,h4,c4), each [4096,25]; owned units only ----
    if (write_states) {
        size_t base = (size_t)Tlen * NB;
        const size_t S = (size_t)NB * 25;
#pragma unroll
        for (int s = 0; s < 2; ++s) {
#pragma unroll
            for (int k = 0; k < 4; ++k) if (k < nu) {
                const int u = first + k;
                size_t idx = (size_t)gbS[s] * 25 + u;
                float h = (layer == 0) ? smem[rowIdx[s] + 1 + u]       // buffer 0
                                       : smem[rowIdx[s] + 26 + u];     // buffer 0
                out[base + (size_t)(2 * layer) * S + idx]     = h;
                out[base + (size_t)(2 * layer + 1) * S + idx] = c[s * 4 + k];
            }
        }
    }
}

extern "C" void kernel_launch(void* const* d_in, const int* in_sizes, int n_in,
                              void* d_out, int out_size) {
    (void)n_in; (void)in_sizes;
    const float* x    = (const float*)d_in[0];
    const float* Wih1 = (const float*)d_in[1];
    const float* Whh1 = (const float*)d_in[2];
    const float* bih1 = (const float*)d_in[3];
    const float* bhh1 = (const float*)d_in[4];
    const float* Wih2 = (const float*)d_in[5];
    const float* Whh2 = (const float*)d_in[6];
    const float* bih2 = (const float*)d_in[7];
    const float* bhh2 = (const float*)d_in[8];
    const float* Wih3 = (const float*)d_in[9];
    const float* Whh3 = (const float*)d_in[10];
    const float* bih3 = (const float*)d_in[11];
    const float* bhh3 = (const float*)d_in[12];
    const float* Wih4 = (const float*)d_in[13];
    const float* Whh4 = (const float*)d_in[14];
    const float* bih4 = (const float*)d_in[15];
    const float* bhh4 = (const float*)d_in[16];
    const float* Wfc  = (const float*)d_in[17];
    const float* bfc  = (const float*)d_in[18];

    int smem_bytes = SMEM_FLOATS * (int)sizeof(float);
    static int configured = -1;
    if (configured != smem_bytes) {
        cudaFuncSetAttribute(lstm_kernel,
                             cudaFuncAttributeMaxDynamicSharedMemorySize, smem_bytes);
        configured = smem_bytes;
    }
    int write_states = (out_size >= Tlen * NB + 8 * NB * 25) ? 1 : 0;

    // 64 clusters x 2 CTAs; each cluster owns 64 batch elements
    lstm_kernel<<<(NB / 64) * CLU, NTHR, smem_bytes>>>(
        x, Wih1, Whh1, bih1, bhh1,
        Wih2, Whh2, bih2, bhh2,
        Wih3, Whh3, bih3, bhh3,
        Wih4, Whh4, bih4, bhh4,
        Wfc, bfc, (float*)d_out, write_states);
}